// round 5
// baseline (speedup 1.0000x reference)
#include <cuda_runtime.h>
#include <cuda_fp16.h>
#include <cuda_bf16.h>
#include <math.h>

// Problem constants (fixed-shape problem)
#define MAXN 50048
#define MAXE 1600000
#define HID 128
#define NH 8
#define HD 16
#define SCAN_BLK 256

// ---------------- device scratch (no allocation allowed) ----------------
__device__ float  g_Q[MAXN * HID];       // fp32 (read once per node)
__device__ __half g_Kh[MAXN * HID];      // fp16 (read per edge)
__device__ __half g_Vh[MAXN * HID];      // fp16 (read per edge)
__device__ int g_cnt[MAXN];
__device__ int g_off[MAXN];
__device__ int g_cur[MAXN];
__device__ int g_esrc[MAXE];
__device__ int g_bsum[512];

// ---------------- QKV GEMM (3xTF32 tensor cores) -------------------------
// C[n,128] = h[n,128] @ W[128,128] + b.  Block tile 128x128, BK=16.
// 256 threads = 8 warps 2(M) x 4(N); warp tile 64x32; mma.m16n8k8.tf32.
// Each operand split hi (tf32) + lo (residual, stored fp16): 3 MMA chains
// give ~fp32 accuracy so the only error left is the fp16 K/V storage.
__device__ __forceinline__ float cvt_tf32f(float v)
{
    unsigned r;
    asm("cvt.rna.tf32.f32 %0, %1;" : "=r"(r) : "f"(v));
    return __uint_as_float(r);
}

__global__ __launch_bounds__(256) void qkv_gemm(
    const float* __restrict__ h,
    const float* __restrict__ wq, const float* __restrict__ bq,
    const float* __restrict__ wk, const float* __restrict__ bk,
    const float* __restrict__ wv, const float* __restrict__ bv,
    int n)
{
    const float* W; const float* bias;
    float*  outf = 0;
    __half* outh = 0;
    if (blockIdx.y == 0)      { W = wq; bias = bq; outf = g_Q; }
    else if (blockIdx.y == 1) { W = wk; bias = bk; outh = g_Kh; }
    else                      { W = wv; bias = bv; outh = g_Vh; }

    __shared__ float  AsH[16][132];   // hi (tf32-rounded)
    __shared__ float  BsH[16][132];
    __shared__ __half AsL[16][132];   // lo residual
    __shared__ __half BsL[16][132];

    const int tid  = threadIdx.x;
    const int lane = tid & 31;
    const int wid  = tid >> 5;          // 0..7
    const int wm   = wid >> 2;          // 0..1 -> M offset wm*64
    const int wn   = wid & 3;           // 0..3 -> N offset wn*32
    const int g    = lane >> 2;         // groupID 0..7
    const int tg   = lane & 3;          // thread-in-group 0..3
    const int row0 = blockIdx.x * 128;

    float c[4][4][4];
#pragma unroll
    for (int mi = 0; mi < 4; mi++)
#pragma unroll
        for (int ni = 0; ni < 4; ni++)
#pragma unroll
            for (int r = 0; r < 4; r++) c[mi][ni][r] = 0.f;

    for (int kk = 0; kk < HID; kk += 16) {
        // A chunk: 128 rows x 16 k. thread: row=tid>>1, 8 cols (2 float4).
        {
            int m    = tid >> 1;
            int base = (tid & 1) * 8;
            int row  = row0 + m;
#pragma unroll
            for (int i = 0; i < 2; i++) {
                float4 v = make_float4(0.f, 0.f, 0.f, 0.f);
                if (row < n)
                    v = *(const float4*)(h + (size_t)row * HID + kk + base + i * 4);
                float vv[4] = {v.x, v.y, v.z, v.w};
#pragma unroll
                for (int j = 0; j < 4; j++) {
                    float hi = cvt_tf32f(vv[j]);
                    AsH[base + i * 4 + j][m] = hi;
                    AsL[base + i * 4 + j][m] = __float2half_rn(vv[j] - hi);
                }
            }
        }
        // B chunk: 16 k x 128 n. thread: k=tid>>4, 8 cols (2 float4).
        {
            int k    = tid >> 4;
            int base = (tid & 15) * 8;
#pragma unroll
            for (int i = 0; i < 2; i++) {
                float4 v = *(const float4*)(W + (size_t)(kk + k) * 128 + base + i * 4);
                float vv[4] = {v.x, v.y, v.z, v.w};
#pragma unroll
                for (int j = 0; j < 4; j++) {
                    float hi = cvt_tf32f(vv[j]);
                    BsH[k][base + i * 4 + j] = hi;
                    BsL[k][base + i * 4 + j] = __float2half_rn(vv[j] - hi);
                }
            }
        }
        __syncthreads();

#pragma unroll
        for (int ks = 0; ks < 2; ks++) {
            const int k0 = ks * 8;
            unsigned aH[4][4], aL[4][4];
#pragma unroll
            for (int mi = 0; mi < 4; mi++) {
                int m0 = wm * 64 + mi * 16;
                aH[mi][0] = __float_as_uint(AsH[k0 + tg    ][m0 + g    ]);
                aH[mi][1] = __float_as_uint(AsH[k0 + tg    ][m0 + g + 8]);
                aH[mi][2] = __float_as_uint(AsH[k0 + tg + 4][m0 + g    ]);
                aH[mi][3] = __float_as_uint(AsH[k0 + tg + 4][m0 + g + 8]);
                aL[mi][0] = __float_as_uint(__half2float(AsL[k0 + tg    ][m0 + g    ]));
                aL[mi][1] = __float_as_uint(__half2float(AsL[k0 + tg    ][m0 + g + 8]));
                aL[mi][2] = __float_as_uint(__half2float(AsL[k0 + tg + 4][m0 + g    ]));
                aL[mi][3] = __float_as_uint(__half2float(AsL[k0 + tg + 4][m0 + g + 8]));
            }
            unsigned bH[4][2], bL[4][2];
#pragma unroll
            for (int ni = 0; ni < 4; ni++) {
                int n0 = wn * 32 + ni * 8;
                bH[ni][0] = __float_as_uint(BsH[k0 + tg    ][n0 + g]);
                bH[ni][1] = __float_as_uint(BsH[k0 + tg + 4][n0 + g]);
                bL[ni][0] = __float_as_uint(__half2float(BsL[k0 + tg    ][n0 + g]));
                bL[ni][1] = __float_as_uint(__half2float(BsL[k0 + tg + 4][n0 + g]));
            }
#pragma unroll
            for (int mi = 0; mi < 4; mi++)
#pragma unroll
                for (int ni = 0; ni < 4; ni++) {
                    // lo terms first (smaller), hi·hi last
                    asm volatile(
                        "mma.sync.aligned.m16n8k8.row.col.f32.tf32.tf32.f32 "
                        "{%0,%1,%2,%3}, {%4,%5,%6,%7}, {%8,%9}, {%0,%1,%2,%3};"
                        : "+f"(c[mi][ni][0]), "+f"(c[mi][ni][1]),
                          "+f"(c[mi][ni][2]), "+f"(c[mi][ni][3])
                        : "r"(aL[mi][0]), "r"(aL[mi][1]), "r"(aL[mi][2]), "r"(aL[mi][3]),
                          "r"(bH[ni][0]), "r"(bH[ni][1]));
                    asm volatile(
                        "mma.sync.aligned.m16n8k8.row.col.f32.tf32.tf32.f32 "
                        "{%0,%1,%2,%3}, {%4,%5,%6,%7}, {%8,%9}, {%0,%1,%2,%3};"
                        : "+f"(c[mi][ni][0]), "+f"(c[mi][ni][1]),
                          "+f"(c[mi][ni][2]), "+f"(c[mi][ni][3])
                        : "r"(aH[mi][0]), "r"(aH[mi][1]), "r"(aH[mi][2]), "r"(aH[mi][3]),
                          "r"(bL[ni][0]), "r"(bL[ni][1]));
                    asm volatile(
                        "mma.sync.aligned.m16n8k8.row.col.f32.tf32.tf32.f32 "
                        "{%0,%1,%2,%3}, {%4,%5,%6,%7}, {%8,%9}, {%0,%1,%2,%3};"
                        : "+f"(c[mi][ni][0]), "+f"(c[mi][ni][1]),
                          "+f"(c[mi][ni][2]), "+f"(c[mi][ni][3])
                        : "r"(aH[mi][0]), "r"(aH[mi][1]), "r"(aH[mi][2]), "r"(aH[mi][3]),
                          "r"(bH[ni][0]), "r"(bH[ni][1]));
                }
        }
        __syncthreads();
    }

    // epilogue: add bias, store (c0,c1 -> row g; c2,c3 -> row g+8)
#pragma unroll
    for (int ni = 0; ni < 4; ni++) {
        int col = wn * 32 + ni * 8 + tg * 2;
        float bx = bias[col], by = bias[col + 1];
#pragma unroll
        for (int mi = 0; mi < 4; mi++) {
            int rowA = row0 + wm * 64 + mi * 16 + g;
            int rowB = rowA + 8;
            if (outf) {
                if (rowA < n) {
                    float2 o = make_float2(c[mi][ni][0] + bx, c[mi][ni][1] + by);
                    *(float2*)(outf + (size_t)rowA * 128 + col) = o;
                }
                if (rowB < n) {
                    float2 o = make_float2(c[mi][ni][2] + bx, c[mi][ni][3] + by);
                    *(float2*)(outf + (size_t)rowB * 128 + col) = o;
                }
            } else {
                if (rowA < n) {
                    __half2 o = __floats2half2_rn(c[mi][ni][0] + bx, c[mi][ni][1] + by);
                    *(__half2*)(outh + (size_t)rowA * 128 + col) = o;
                }
                if (rowB < n) {
                    __half2 o = __floats2half2_rn(c[mi][ni][2] + bx, c[mi][ni][3] + by);
                    *(__half2*)(outh + (size_t)rowB * 128 + col) = o;
                }
            }
        }
    }
}

// ---------------- CSR construction --------------------------------------
__global__ void zero_cnt(int n)
{
    int i = blockIdx.x * blockDim.x + threadIdx.x;
    if (i < n) g_cnt[i] = 0;
}

__global__ void hist_kernel(const int* __restrict__ dst, int E)
{
    int i = blockIdx.x * blockDim.x + threadIdx.x;
    if (i < E) atomicAdd(&g_cnt[dst[i]], 1);
}

__global__ __launch_bounds__(SCAN_BLK) void scan_partial(int n)
{
    __shared__ int sh[SCAN_BLK];
    int i = blockIdx.x * SCAN_BLK + threadIdx.x;
    int v = (i < n) ? g_cnt[i] : 0;
    sh[threadIdx.x] = v;
    __syncthreads();
    for (int off = SCAN_BLK / 2; off > 0; off >>= 1) {
        if (threadIdx.x < off) sh[threadIdx.x] += sh[threadIdx.x + off];
        __syncthreads();
    }
    if (threadIdx.x == 0) g_bsum[blockIdx.x] = sh[0];
}

__global__ __launch_bounds__(SCAN_BLK) void scan_bsums(int nb)
{
    __shared__ int sh[SCAN_BLK];
    int t = threadIdx.x;
    int v = (t < nb) ? g_bsum[t] : 0;
    sh[t] = v;
    __syncthreads();
    for (int off = 1; off < SCAN_BLK; off <<= 1) {
        int u = (t >= off) ? sh[t - off] : 0;
        __syncthreads();
        sh[t] += u;
        __syncthreads();
    }
    if (t < nb) g_bsum[t] = sh[t] - v;   // exclusive
}

__global__ __launch_bounds__(SCAN_BLK) void scan_final(int n)
{
    __shared__ int sh[SCAN_BLK];
    int i = blockIdx.x * SCAN_BLK + threadIdx.x;
    int t = threadIdx.x;
    int v = (i < n) ? g_cnt[i] : 0;
    sh[t] = v;
    __syncthreads();
    for (int off = 1; off < SCAN_BLK; off <<= 1) {
        int u = (t >= off) ? sh[t - off] : 0;
        __syncthreads();
        sh[t] += u;
        __syncthreads();
    }
    if (i < n) {
        int excl = sh[t] - v + g_bsum[blockIdx.x];
        g_off[i] = excl;
        g_cur[i] = excl;
    }
}

__global__ void scatter_kernel(const int* __restrict__ src,
                               const int* __restrict__ dst, int E)
{
    int i = blockIdx.x * blockDim.x + threadIdx.x;
    if (i < E) {
        int p = atomicAdd(&g_cur[dst[i]], 1);
        g_esrc[p] = src[i];
    }
}

// ---------------- gather: one warp per destination node ------------------
// lane l owns dims [l*4, l*4+4). head = l/4 (4 lanes x 4 dims = 16 dims/head).
// K/V in fp16: each lane loads 8 bytes per row (2x half2).
__global__ __launch_bounds__(256) void gat_gather(float* __restrict__ out, int n)
{
    int warp = (blockIdx.x * blockDim.x + threadIdx.x) >> 5;
    int lane = threadIdx.x & 31;
    if (warp >= n) return;

    const int t = lane * 4;
    const int start = g_off[warp];
    const int end   = g_cur[warp];

    const float4 q = *(const float4*)(g_Q + (size_t)warp * 128 + t);

    float ax = 0.f, ay = 0.f, az = 0.f, aw = 0.f;
    float den = 0.f;

    int s_next = (start < end) ? g_esrc[start] : 0;
    for (int i = start; i < end; i++) {
        int s = s_next;                    // uniform across warp (broadcast)
        if (i + 1 < end) s_next = g_esrc[i + 1];   // prefetch next index
        uint2 kraw = *(const uint2*)(g_Kh + (size_t)s * 128 + t);
        float2 k01 = __half22float2(*(__half2*)&kraw.x);
        float2 k23 = __half22float2(*(__half2*)&kraw.y);
        float p = q.x * k01.x + q.y * k01.y + q.z * k23.x + q.w * k23.y;
        p += __shfl_xor_sync(0xFFFFFFFFu, p, 1);
        p += __shfl_xor_sync(0xFFFFFFFFu, p, 2);
        float e = __expf(p * 0.25f);       // 1/sqrt(D), D=16
        uint2 vraw = *(const uint2*)(g_Vh + (size_t)s * 128 + t);
        float2 v01 = __half22float2(*(__half2*)&vraw.x);
        float2 v23 = __half22float2(*(__half2*)&vraw.y);
        ax = fmaf(e, v01.x, ax);
        ay = fmaf(e, v01.y, ay);
        az = fmaf(e, v23.x, az);
        aw = fmaf(e, v23.y, aw);
        den += e;
    }

    float inv = 1.f / den;
    float4 o;
    o.x = ax * inv; o.y = ay * inv; o.z = az * inv; o.w = aw * inv;
    *(float4*)(out + (size_t)warp * 128 + t) = o;
}

// ---------------- launch ------------------------------------------------
extern "C" void kernel_launch(void* const* d_in, const int* in_sizes, int n_in,
                              void* d_out, int out_size)
{
    const float* h  = (const float*)d_in[0];
    const float* wq = (const float*)d_in[1];
    const float* bq = (const float*)d_in[2];
    const float* wk = (const float*)d_in[3];
    const float* bk = (const float*)d_in[4];
    const float* wv = (const float*)d_in[5];
    const float* bv = (const float*)d_in[6];
    const int*  src = (const int*)d_in[7];
    const int*  dst = (const int*)d_in[8];

    const int n = in_sizes[0] / HID;
    const int E = in_sizes[7];
    const int nb = (n + SCAN_BLK - 1) / SCAN_BLK;

    float* out = (float*)d_out;

    // 1) Q,K,V GEMMs (3xTF32; Q fp32, K/V fp16 outputs)
    {
        dim3 grid((n + 127) / 128, 3);
        qkv_gemm<<<grid, 256>>>(h, wq, bq, wk, bk, wv, bv, n);
    }
    // 2) CSR build (parallel 3-stage scan)
    zero_cnt<<<(n + 255) / 256, 256>>>(n);
    hist_kernel<<<(E + 255) / 256, 256>>>(dst, E);
    scan_partial<<<nb, SCAN_BLK>>>(n);
    scan_bsums<<<1, SCAN_BLK>>>(nb);
    scan_final<<<nb, SCAN_BLK>>>(n);
    scatter_kernel<<<(E + 255) / 256, 256>>>(src, dst, E);
    // 3) gather (one warp per node, 8 warps/block)
    gat_gather<<<(n + 7) / 8, 256>>>(out, n);
}

// round 6
// speedup vs baseline: 1.0600x; 1.0600x over previous
#include <cuda_runtime.h>
#include <cuda_fp16.h>
#include <cuda_bf16.h>
#include <math.h>

// Problem constants (fixed-shape problem)
#define MAXN 50048
#define MAXE 1600000
#define HID 128
#define NH 8
#define HD 16
#define SCAN_BLK 256

// ---------------- device scratch (no allocation allowed) ----------------
__device__ float  g_Q[MAXN * HID];       // fp32 (read once per node)
__device__ __half g_Kh[MAXN * HID];      // fp16 (read per edge)
__device__ __half g_Vh[MAXN * HID];      // fp16 (read per edge)
__device__ int g_cnt[MAXN];
__device__ int g_off[MAXN];
__device__ int g_cur[MAXN];
__device__ int g_esrc[MAXE];
__device__ int g_bsum[512];

// ---------------- QKV GEMM (tf32 tensor cores, A-residual corrected) -----
// C[n,128] = h[n,128] @ W[128,128] + b.  Block tile 128x128, BK=32.
// 256 threads = 8 warps 2(M) x 4(N); warp tile 64x32; mma.m16n8k8.tf32.
// A split: hi=tf32(a), lo=fp16(a-hi). Two MMA chains (aL*bH + aH*bH) remove
// the A-operand tf32 rounding; only W rounding remains (~1e-4).
__device__ __forceinline__ float cvt_tf32f(float v)
{
    unsigned r;
    asm("cvt.rna.tf32.f32 %0, %1;" : "=r"(r) : "f"(v));
    return __uint_as_float(r);
}

__global__ __launch_bounds__(256) void qkv_gemm(
    const float* __restrict__ h,
    const float* __restrict__ wq, const float* __restrict__ bq,
    const float* __restrict__ wk, const float* __restrict__ bk,
    const float* __restrict__ wv, const float* __restrict__ bv,
    int n)
{
    const float* W; const float* bias;
    float*  outf = 0;
    __half* outh = 0;
    if (blockIdx.y == 0)      { W = wq; bias = bq; outf = g_Q; }
    else if (blockIdx.y == 1) { W = wk; bias = bk; outh = g_Kh; }
    else                      { W = wv; bias = bv; outh = g_Vh; }

    __shared__ float  As[32][132];    // A hi (tf32-rounded), [k][m]
    __shared__ float  Bs[32][132];    // B hi (tf32-rounded), [k][n]
    __shared__ __half AsL[32][132];   // A lo residual

    const int tid  = threadIdx.x;
    const int lane = tid & 31;
    const int wid  = tid >> 5;          // 0..7
    const int wm   = wid >> 2;          // 0..1 -> M offset wm*64
    const int wn   = wid & 3;           // 0..3 -> N offset wn*32
    const int g    = lane >> 2;         // groupID 0..7
    const int tg   = lane & 3;          // thread-in-group 0..3
    const int row0 = blockIdx.x * 128;

    float c[4][4][4];
#pragma unroll
    for (int mi = 0; mi < 4; mi++)
#pragma unroll
        for (int ni = 0; ni < 4; ni++)
#pragma unroll
            for (int r = 0; r < 4; r++) c[mi][ni][r] = 0.f;

    for (int kk = 0; kk < HID; kk += 32) {
        // A chunk: 128 rows x 32 k. thread: row=tid>>1, 16 cols.
        {
            int m    = tid >> 1;
            int base = (tid & 1) * 16;
            int row  = row0 + m;
#pragma unroll
            for (int i = 0; i < 4; i++) {
                float4 v = make_float4(0.f, 0.f, 0.f, 0.f);
                if (row < n)
                    v = *(const float4*)(h + (size_t)row * HID + kk + base + i * 4);
                float vv[4] = {v.x, v.y, v.z, v.w};
#pragma unroll
                for (int j = 0; j < 4; j++) {
                    float hi = cvt_tf32f(vv[j]);
                    As[base + i * 4 + j][m]  = hi;
                    AsL[base + i * 4 + j][m] = __float2half_rn(vv[j] - hi);
                }
            }
        }
        // B chunk: 32 k x 128 n. thread: k=tid>>3, 16 cols.
        {
            int k    = tid >> 3;
            int base = (tid & 7) * 16;
#pragma unroll
            for (int i = 0; i < 4; i++) {
                float4 v = *(const float4*)(W + (size_t)(kk + k) * 128 + base + i * 4);
                Bs[k][base + i * 4 + 0] = cvt_tf32f(v.x);
                Bs[k][base + i * 4 + 1] = cvt_tf32f(v.y);
                Bs[k][base + i * 4 + 2] = cvt_tf32f(v.z);
                Bs[k][base + i * 4 + 3] = cvt_tf32f(v.w);
            }
        }
        __syncthreads();

#pragma unroll
        for (int ks = 0; ks < 4; ks++) {
            const int k0 = ks * 8;
            unsigned a[4][4], aL[4][4];
#pragma unroll
            for (int mi = 0; mi < 4; mi++) {
                int m0 = wm * 64 + mi * 16;
                a[mi][0] = __float_as_uint(As[k0 + tg    ][m0 + g    ]);
                a[mi][1] = __float_as_uint(As[k0 + tg    ][m0 + g + 8]);
                a[mi][2] = __float_as_uint(As[k0 + tg + 4][m0 + g    ]);
                a[mi][3] = __float_as_uint(As[k0 + tg + 4][m0 + g + 8]);
                aL[mi][0] = __float_as_uint(__half2float(AsL[k0 + tg    ][m0 + g    ]));
                aL[mi][1] = __float_as_uint(__half2float(AsL[k0 + tg    ][m0 + g + 8]));
                aL[mi][2] = __float_as_uint(__half2float(AsL[k0 + tg + 4][m0 + g    ]));
                aL[mi][3] = __float_as_uint(__half2float(AsL[k0 + tg + 4][m0 + g + 8]));
            }
            unsigned b[4][2];
#pragma unroll
            for (int ni = 0; ni < 4; ni++) {
                int n0 = wn * 32 + ni * 8;
                b[ni][0] = __float_as_uint(Bs[k0 + tg    ][n0 + g]);
                b[ni][1] = __float_as_uint(Bs[k0 + tg + 4][n0 + g]);
            }
#pragma unroll
            for (int mi = 0; mi < 4; mi++)
#pragma unroll
                for (int ni = 0; ni < 4; ni++) {
                    asm volatile(
                        "mma.sync.aligned.m16n8k8.row.col.f32.tf32.tf32.f32 "
                        "{%0,%1,%2,%3}, {%4,%5,%6,%7}, {%8,%9}, {%0,%1,%2,%3};"
                        : "+f"(c[mi][ni][0]), "+f"(c[mi][ni][1]),
                          "+f"(c[mi][ni][2]), "+f"(c[mi][ni][3])
                        : "r"(aL[mi][0]), "r"(aL[mi][1]), "r"(aL[mi][2]), "r"(aL[mi][3]),
                          "r"(b[ni][0]), "r"(b[ni][1]));
                    asm volatile(
                        "mma.sync.aligned.m16n8k8.row.col.f32.tf32.tf32.f32 "
                        "{%0,%1,%2,%3}, {%4,%5,%6,%7}, {%8,%9}, {%0,%1,%2,%3};"
                        : "+f"(c[mi][ni][0]), "+f"(c[mi][ni][1]),
                          "+f"(c[mi][ni][2]), "+f"(c[mi][ni][3])
                        : "r"(a[mi][0]), "r"(a[mi][1]), "r"(a[mi][2]), "r"(a[mi][3]),
                          "r"(b[ni][0]), "r"(b[ni][1]));
                }
        }
        __syncthreads();
    }

    // epilogue: add bias, store (c0,c1 -> row g; c2,c3 -> row g+8)
#pragma unroll
    for (int ni = 0; ni < 4; ni++) {
        int col = wn * 32 + ni * 8 + tg * 2;
        float bx = bias[col], by = bias[col + 1];
#pragma unroll
        for (int mi = 0; mi < 4; mi++) {
            int rowA = row0 + wm * 64 + mi * 16 + g;
            int rowB = rowA + 8;
            if (outf) {
                if (rowA < n) {
                    float2 o = make_float2(c[mi][ni][0] + bx, c[mi][ni][1] + by);
                    *(float2*)(outf + (size_t)rowA * 128 + col) = o;
                }
                if (rowB < n) {
                    float2 o = make_float2(c[mi][ni][2] + bx, c[mi][ni][3] + by);
                    *(float2*)(outf + (size_t)rowB * 128 + col) = o;
                }
            } else {
                if (rowA < n) {
                    __half2 o = __floats2half2_rn(c[mi][ni][0] + bx, c[mi][ni][1] + by);
                    *(__half2*)(outh + (size_t)rowA * 128 + col) = o;
                }
                if (rowB < n) {
                    __half2 o = __floats2half2_rn(c[mi][ni][2] + bx, c[mi][ni][3] + by);
                    *(__half2*)(outh + (size_t)rowB * 128 + col) = o;
                }
            }
        }
    }
}

// ---------------- CSR construction --------------------------------------
__global__ void zero_cnt(int n)
{
    int i = blockIdx.x * blockDim.x + threadIdx.x;
    if (i < n) g_cnt[i] = 0;
}

__global__ void hist_kernel(const int* __restrict__ dst, int E)
{
    int i = blockIdx.x * blockDim.x + threadIdx.x;
    if (i < E) atomicAdd(&g_cnt[dst[i]], 1);
}

__global__ __launch_bounds__(SCAN_BLK) void scan_partial(int n)
{
    __shared__ int sh[SCAN_BLK];
    int i = blockIdx.x * SCAN_BLK + threadIdx.x;
    int v = (i < n) ? g_cnt[i] : 0;
    sh[threadIdx.x] = v;
    __syncthreads();
    for (int off = SCAN_BLK / 2; off > 0; off >>= 1) {
        if (threadIdx.x < off) sh[threadIdx.x] += sh[threadIdx.x + off];
        __syncthreads();
    }
    if (threadIdx.x == 0) g_bsum[blockIdx.x] = sh[0];
}

__global__ __launch_bounds__(SCAN_BLK) void scan_bsums(int nb)
{
    __shared__ int sh[SCAN_BLK];
    int t = threadIdx.x;
    int v = (t < nb) ? g_bsum[t] : 0;
    sh[t] = v;
    __syncthreads();
    for (int off = 1; off < SCAN_BLK; off <<= 1) {
        int u = (t >= off) ? sh[t - off] : 0;
        __syncthreads();
        sh[t] += u;
        __syncthreads();
    }
    if (t < nb) g_bsum[t] = sh[t] - v;   // exclusive
}

__global__ __launch_bounds__(SCAN_BLK) void scan_final(int n)
{
    __shared__ int sh[SCAN_BLK];
    int i = blockIdx.x * SCAN_BLK + threadIdx.x;
    int t = threadIdx.x;
    int v = (i < n) ? g_cnt[i] : 0;
    sh[t] = v;
    __syncthreads();
    for (int off = 1; off < SCAN_BLK; off <<= 1) {
        int u = (t >= off) ? sh[t - off] : 0;
        __syncthreads();
        sh[t] += u;
        __syncthreads();
    }
    if (i < n) {
        int excl = sh[t] - v + g_bsum[blockIdx.x];
        g_off[i] = excl;
        g_cur[i] = excl;
    }
}

__global__ void scatter_kernel(const int* __restrict__ src,
                               const int* __restrict__ dst, int E)
{
    int i = blockIdx.x * blockDim.x + threadIdx.x;
    if (i < E) {
        int p = atomicAdd(&g_cur[dst[i]], 1);
        g_esrc[p] = src[i];
    }
}

// ---------------- gather: one warp per destination node ------------------
// lane l owns dims [l*4, l*4+4). head = l/4 (4 lanes x 4 dims = 16 dims/head).
// K/V in fp16: each lane loads 8 bytes per row (2x half2).
__global__ __launch_bounds__(256) void gat_gather(float* __restrict__ out, int n)
{
    int warp = (blockIdx.x * blockDim.x + threadIdx.x) >> 5;
    int lane = threadIdx.x & 31;
    if (warp >= n) return;

    const int t = lane * 4;
    const int start = g_off[warp];
    const int end   = g_cur[warp];

    const float4 q = *(const float4*)(g_Q + (size_t)warp * 128 + t);

    float ax = 0.f, ay = 0.f, az = 0.f, aw = 0.f;
    float den = 0.f;

    int s_next = (start < end) ? g_esrc[start] : 0;
    for (int i = start; i < end; i++) {
        int s = s_next;                    // uniform across warp (broadcast)
        if (i + 1 < end) s_next = g_esrc[i + 1];   // prefetch next index
        uint2 kraw = *(const uint2*)(g_Kh + (size_t)s * 128 + t);
        float2 k01 = __half22float2(*(__half2*)&kraw.x);
        float2 k23 = __half22float2(*(__half2*)&kraw.y);
        float p = q.x * k01.x + q.y * k01.y + q.z * k23.x + q.w * k23.y;
        p += __shfl_xor_sync(0xFFFFFFFFu, p, 1);
        p += __shfl_xor_sync(0xFFFFFFFFu, p, 2);
        float e = __expf(p * 0.25f);       // 1/sqrt(D), D=16
        uint2 vraw = *(const uint2*)(g_Vh + (size_t)s * 128 + t);
        float2 v01 = __half22float2(*(__half2*)&vraw.x);
        float2 v23 = __half22float2(*(__half2*)&vraw.y);
        ax = fmaf(e, v01.x, ax);
        ay = fmaf(e, v01.y, ay);
        az = fmaf(e, v23.x, az);
        aw = fmaf(e, v23.y, aw);
        den += e;
    }

    float inv = 1.f / den;
    float4 o;
    o.x = ax * inv; o.y = ay * inv; o.z = az * inv; o.w = aw * inv;
    *(float4*)(out + (size_t)warp * 128 + t) = o;
}

// ---------------- launch ------------------------------------------------
extern "C" void kernel_launch(void* const* d_in, const int* in_sizes, int n_in,
                              void* d_out, int out_size)
{
    const float* h  = (const float*)d_in[0];
    const float* wq = (const float*)d_in[1];
    const float* bq = (const float*)d_in[2];
    const float* wk = (const float*)d_in[3];
    const float* bk = (const float*)d_in[4];
    const float* wv = (const float*)d_in[5];
    const float* bv = (const float*)d_in[6];
    const int*  src = (const int*)d_in[7];
    const int*  dst = (const int*)d_in[8];

    const int n = in_sizes[0] / HID;
    const int E = in_sizes[7];
    const int nb = (n + SCAN_BLK - 1) / SCAN_BLK;

    float* out = (float*)d_out;

    // 1) Q,K,V GEMMs (tf32 + A-residual correction; Q fp32, K/V fp16 out)
    {
        dim3 grid((n + 127) / 128, 3);
        qkv_gemm<<<grid, 256>>>(h, wq, bq, wk, bk, wv, bv, n);
    }
    // 2) CSR build (parallel 3-stage scan)
    zero_cnt<<<(n + 255) / 256, 256>>>(n);
    hist_kernel<<<(E + 255) / 256, 256>>>(dst, E);
    scan_partial<<<nb, SCAN_BLK>>>(n);
    scan_bsums<<<1, SCAN_BLK>>>(nb);
    scan_final<<<nb, SCAN_BLK>>>(n);
    scatter_kernel<<<(E + 255) / 256, 256>>>(src, dst, E);
    // 3) gather (one warp per node, 8 warps/block)
    gat_gather<<<(n + 7) / 8, 256>>>(out, n);
}

// round 7
// speedup vs baseline: 1.2467x; 1.1761x over previous
#include <cuda_runtime.h>
#include <cuda_fp16.h>
#include <cuda_bf16.h>
#include <math.h>

// Problem constants (fixed-shape problem)
#define MAXN 50048
#define MAXE 1600000
#define HID 128
#define NH 8
#define HD 16
#define SCAN_BLK 256

// ---------------- device scratch (no allocation allowed) ----------------
__device__ float  g_Q[MAXN * HID];       // fp32 (read once per node)
__device__ __half g_Kh[MAXN * HID];      // fp16 (read per edge)
__device__ __half g_Vh[MAXN * HID];      // fp16 (read per edge)
__device__ int g_cnt[MAXN];              // zero-initialized; re-zeroed in scan_final
__device__ int g_off[MAXN];
__device__ int g_cur[MAXN];
__device__ int g_esrc[MAXE];
__device__ int g_bsum[512];

// ---------------- QKV GEMM (tf32 tensor cores) ---------------------------
// C[n,128] = h[n,128] @ W[128,128] + b.  Block tile 128x128, BK=32.
// 256 threads = 8 warps 2(M) x 4(N); warp tile 64x32; mma.m16n8k8.tf32.
__device__ __forceinline__ float cvt_tf32f(float v)
{
    unsigned r;
    asm("cvt.rna.tf32.f32 %0, %1;" : "=r"(r) : "f"(v));
    return __uint_as_float(r);
}

__global__ __launch_bounds__(256) void qkv_gemm(
    const float* __restrict__ h,
    const float* __restrict__ wq, const float* __restrict__ bq,
    const float* __restrict__ wk, const float* __restrict__ bk,
    const float* __restrict__ wv, const float* __restrict__ bv,
    int n)
{
    const float* W; const float* bias;
    float*  outf = 0;
    __half* outh = 0;
    if (blockIdx.y == 0)      { W = wq; bias = bq; outf = g_Q; }
    else if (blockIdx.y == 1) { W = wk; bias = bk; outh = g_Kh; }
    else                      { W = wv; bias = bv; outh = g_Vh; }

    __shared__ float As[32][132];   // [k][m], tf32-rounded
    __shared__ float Bs[32][132];   // [k][n], tf32-rounded

    const int tid  = threadIdx.x;
    const int lane = tid & 31;
    const int wid  = tid >> 5;          // 0..7
    const int wm   = wid >> 2;          // 0..1 -> M offset wm*64
    const int wn   = wid & 3;           // 0..3 -> N offset wn*32
    const int g    = lane >> 2;         // groupID 0..7
    const int tg   = lane & 3;          // thread-in-group 0..3
    const int row0 = blockIdx.x * 128;

    float c[4][4][4];
#pragma unroll
    for (int mi = 0; mi < 4; mi++)
#pragma unroll
        for (int ni = 0; ni < 4; ni++)
#pragma unroll
            for (int r = 0; r < 4; r++) c[mi][ni][r] = 0.f;

    for (int kk = 0; kk < HID; kk += 32) {
        {
            int m    = tid >> 1;
            int base = (tid & 1) * 16;
            int row  = row0 + m;
#pragma unroll
            for (int i = 0; i < 4; i++) {
                float4 v = make_float4(0.f, 0.f, 0.f, 0.f);
                if (row < n)
                    v = *(const float4*)(h + (size_t)row * HID + kk + base + i * 4);
                As[base + i * 4 + 0][m] = cvt_tf32f(v.x);
                As[base + i * 4 + 1][m] = cvt_tf32f(v.y);
                As[base + i * 4 + 2][m] = cvt_tf32f(v.z);
                As[base + i * 4 + 3][m] = cvt_tf32f(v.w);
            }
        }
        {
            int k    = tid >> 3;
            int base = (tid & 7) * 16;
#pragma unroll
            for (int i = 0; i < 4; i++) {
                float4 v = *(const float4*)(W + (size_t)(kk + k) * 128 + base + i * 4);
                Bs[k][base + i * 4 + 0] = cvt_tf32f(v.x);
                Bs[k][base + i * 4 + 1] = cvt_tf32f(v.y);
                Bs[k][base + i * 4 + 2] = cvt_tf32f(v.z);
                Bs[k][base + i * 4 + 3] = cvt_tf32f(v.w);
            }
        }
        __syncthreads();

#pragma unroll
        for (int ks = 0; ks < 4; ks++) {
            const int k0 = ks * 8;
            unsigned a[4][4];
#pragma unroll
            for (int mi = 0; mi < 4; mi++) {
                int m0 = wm * 64 + mi * 16;
                a[mi][0] = __float_as_uint(As[k0 + tg    ][m0 + g    ]);
                a[mi][1] = __float_as_uint(As[k0 + tg    ][m0 + g + 8]);
                a[mi][2] = __float_as_uint(As[k0 + tg + 4][m0 + g    ]);
                a[mi][3] = __float_as_uint(As[k0 + tg + 4][m0 + g + 8]);
            }
            unsigned b[4][2];
#pragma unroll
            for (int ni = 0; ni < 4; ni++) {
                int n0 = wn * 32 + ni * 8;
                b[ni][0] = __float_as_uint(Bs[k0 + tg    ][n0 + g]);
                b[ni][1] = __float_as_uint(Bs[k0 + tg + 4][n0 + g]);
            }
#pragma unroll
            for (int mi = 0; mi < 4; mi++)
#pragma unroll
                for (int ni = 0; ni < 4; ni++) {
                    asm volatile(
                        "mma.sync.aligned.m16n8k8.row.col.f32.tf32.tf32.f32 "
                        "{%0,%1,%2,%3}, {%4,%5,%6,%7}, {%8,%9}, {%0,%1,%2,%3};"
                        : "+f"(c[mi][ni][0]), "+f"(c[mi][ni][1]),
                          "+f"(c[mi][ni][2]), "+f"(c[mi][ni][3])
                        : "r"(a[mi][0]), "r"(a[mi][1]), "r"(a[mi][2]), "r"(a[mi][3]),
                          "r"(b[ni][0]), "r"(b[ni][1]));
                }
        }
        __syncthreads();
    }

    // epilogue: add bias, store (c0,c1 -> row g; c2,c3 -> row g+8)
#pragma unroll
    for (int ni = 0; ni < 4; ni++) {
        int col = wn * 32 + ni * 8 + tg * 2;
        float bx = bias[col], by = bias[col + 1];
#pragma unroll
        for (int mi = 0; mi < 4; mi++) {
            int rowA = row0 + wm * 64 + mi * 16 + g;
            int rowB = rowA + 8;
            if (outf) {
                if (rowA < n) {
                    float2 o = make_float2(c[mi][ni][0] + bx, c[mi][ni][1] + by);
                    *(float2*)(outf + (size_t)rowA * 128 + col) = o;
                }
                if (rowB < n) {
                    float2 o = make_float2(c[mi][ni][2] + bx, c[mi][ni][3] + by);
                    *(float2*)(outf + (size_t)rowB * 128 + col) = o;
                }
            } else {
                if (rowA < n) {
                    __half2 o = __floats2half2_rn(c[mi][ni][0] + bx, c[mi][ni][1] + by);
                    *(__half2*)(outh + (size_t)rowA * 128 + col) = o;
                }
                if (rowB < n) {
                    __half2 o = __floats2half2_rn(c[mi][ni][2] + bx, c[mi][ni][3] + by);
                    *(__half2*)(outh + (size_t)rowB * 128 + col) = o;
                }
            }
        }
    }
}

// ---------------- CSR construction --------------------------------------
__global__ void hist_kernel(const int* __restrict__ dst, int E)
{
    int i = blockIdx.x * blockDim.x + threadIdx.x;
    if (i < E) atomicAdd(&g_cnt[dst[i]], 1);
}

__global__ __launch_bounds__(SCAN_BLK) void scan_partial(int n)
{
    __shared__ int sh[SCAN_BLK];
    int i = blockIdx.x * SCAN_BLK + threadIdx.x;
    int v = (i < n) ? g_cnt[i] : 0;
    sh[threadIdx.x] = v;
    __syncthreads();
    for (int off = SCAN_BLK / 2; off > 0; off >>= 1) {
        if (threadIdx.x < off) sh[threadIdx.x] += sh[threadIdx.x + off];
        __syncthreads();
    }
    if (threadIdx.x == 0) g_bsum[blockIdx.x] = sh[0];
}

__global__ __launch_bounds__(SCAN_BLK) void scan_bsums(int nb)
{
    __shared__ int sh[SCAN_BLK];
    int t = threadIdx.x;
    int v = (t < nb) ? g_bsum[t] : 0;
    sh[t] = v;
    __syncthreads();
    for (int off = 1; off < SCAN_BLK; off <<= 1) {
        int u = (t >= off) ? sh[t - off] : 0;
        __syncthreads();
        sh[t] += u;
        __syncthreads();
    }
    if (t < nb) g_bsum[t] = sh[t] - v;   // exclusive
}

// reads g_cnt, writes g_off/g_cur, and re-zeroes g_cnt for the next call
// (statics start zeroed, every call leaves them zeroed -> deterministic).
__global__ __launch_bounds__(SCAN_BLK) void scan_final(int n)
{
    __shared__ int sh[SCAN_BLK];
    int i = blockIdx.x * SCAN_BLK + threadIdx.x;
    int t = threadIdx.x;
    int v = (i < n) ? g_cnt[i] : 0;
    sh[t] = v;
    __syncthreads();
    for (int off = 1; off < SCAN_BLK; off <<= 1) {
        int u = (t >= off) ? sh[t - off] : 0;
        __syncthreads();
        sh[t] += u;
        __syncthreads();
    }
    if (i < n) {
        int excl = sh[t] - v + g_bsum[blockIdx.x];
        g_off[i] = excl;
        g_cur[i] = excl;
        g_cnt[i] = 0;
    }
}

__global__ void scatter_kernel(const int* __restrict__ src,
                               const int* __restrict__ dst, int E)
{
    int i = blockIdx.x * blockDim.x + threadIdx.x;
    if (i < E) {
        int p = atomicAdd(&g_cur[dst[i]], 1);
        g_esrc[p] = src[i];
    }
}

// ---------------- gather: one warp per destination node ------------------
// lane l owns dims [l*4, l*4+4). head = l/4 (4 lanes x 4 dims = 16 dims/head).
// K/V in fp16 (uint2 per lane). 2-way unrolled for MLP.
__global__ __launch_bounds__(256) void gat_gather(float* __restrict__ out, int n)
{
    int warp = (blockIdx.x * blockDim.x + threadIdx.x) >> 5;
    int lane = threadIdx.x & 31;
    if (warp >= n) return;

    const int t = lane * 4;
    const int start = g_off[warp];
    const int end   = g_cur[warp];

    const float4 q = *(const float4*)(g_Q + (size_t)warp * 128 + t);

    float ax = 0.f, ay = 0.f, az = 0.f, aw = 0.f;
    float den = 0.f;

    int i = start;
    for (; i + 1 < end; i += 2) {
        int s0 = g_esrc[i];
        int s1 = g_esrc[i + 1];
        uint2 kraw0 = *(const uint2*)(g_Kh + (size_t)s0 * 128 + t);
        uint2 kraw1 = *(const uint2*)(g_Kh + (size_t)s1 * 128 + t);
        uint2 vraw0 = *(const uint2*)(g_Vh + (size_t)s0 * 128 + t);
        uint2 vraw1 = *(const uint2*)(g_Vh + (size_t)s1 * 128 + t);

        float2 k01 = __half22float2(*(__half2*)&kraw0.x);
        float2 k23 = __half22float2(*(__half2*)&kraw0.y);
        float p0 = q.x * k01.x + q.y * k01.y + q.z * k23.x + q.w * k23.y;
        float2 l01 = __half22float2(*(__half2*)&kraw1.x);
        float2 l23 = __half22float2(*(__half2*)&kraw1.y);
        float p1 = q.x * l01.x + q.y * l01.y + q.z * l23.x + q.w * l23.y;

        p0 += __shfl_xor_sync(0xFFFFFFFFu, p0, 1);
        p1 += __shfl_xor_sync(0xFFFFFFFFu, p1, 1);
        p0 += __shfl_xor_sync(0xFFFFFFFFu, p0, 2);
        p1 += __shfl_xor_sync(0xFFFFFFFFu, p1, 2);
        float e0 = __expf(p0 * 0.25f);
        float e1 = __expf(p1 * 0.25f);

        float2 v01 = __half22float2(*(__half2*)&vraw0.x);
        float2 v23 = __half22float2(*(__half2*)&vraw0.y);
        float2 w01 = __half22float2(*(__half2*)&vraw1.x);
        float2 w23 = __half22float2(*(__half2*)&vraw1.y);
        ax = fmaf(e0, v01.x, fmaf(e1, w01.x, ax));
        ay = fmaf(e0, v01.y, fmaf(e1, w01.y, ay));
        az = fmaf(e0, v23.x, fmaf(e1, w23.x, az));
        aw = fmaf(e0, v23.y, fmaf(e1, w23.y, aw));
        den += e0 + e1;
    }
    if (i < end) {
        int s = g_esrc[i];
        uint2 kraw = *(const uint2*)(g_Kh + (size_t)s * 128 + t);
        float2 k01 = __half22float2(*(__half2*)&kraw.x);
        float2 k23 = __half22float2(*(__half2*)&kraw.y);
        float p = q.x * k01.x + q.y * k01.y + q.z * k23.x + q.w * k23.y;
        p += __shfl_xor_sync(0xFFFFFFFFu, p, 1);
        p += __shfl_xor_sync(0xFFFFFFFFu, p, 2);
        float e = __expf(p * 0.25f);
        uint2 vraw = *(const uint2*)(g_Vh + (size_t)s * 128 + t);
        float2 v01 = __half22float2(*(__half2*)&vraw.x);
        float2 v23 = __half22float2(*(__half2*)&vraw.y);
        ax = fmaf(e, v01.x, ax);
        ay = fmaf(e, v01.y, ay);
        az = fmaf(e, v23.x, az);
        aw = fmaf(e, v23.y, aw);
        den += e;
    }

    float inv = 1.f / den;
    float4 o;
    o.x = ax * inv; o.y = ay * inv; o.z = az * inv; o.w = aw * inv;
    *(float4*)(out + (size_t)warp * 128 + t) = o;
}

// ---------------- launch ------------------------------------------------
extern "C" void kernel_launch(void* const* d_in, const int* in_sizes, int n_in,
                              void* d_out, int out_size)
{
    const float* h  = (const float*)d_in[0];
    const float* wq = (const float*)d_in[1];
    const float* bq = (const float*)d_in[2];
    const float* wk = (const float*)d_in[3];
    const float* bk = (const float*)d_in[4];
    const float* wv = (const float*)d_in[5];
    const float* bv = (const float*)d_in[6];
    const int*  src = (const int*)d_in[7];
    const int*  dst = (const int*)d_in[8];

    const int n = in_sizes[0] / HID;
    const int E = in_sizes[7];
    const int nb = (n + SCAN_BLK - 1) / SCAN_BLK;

    float* out = (float*)d_out;

    // 1) Q,K,V GEMMs (tf32; Q fp32, K/V fp16 outputs)
    {
        dim3 grid((n + 127) / 128, 3);
        qkv_gemm<<<grid, 256>>>(h, wq, bq, wk, bk, wv, bv, n);
    }
    // 2) CSR build (g_cnt is zeroed at start: statics init + scan_final re-zero)
    hist_kernel<<<(E + 255) / 256, 256>>>(dst, E);
    scan_partial<<<nb, SCAN_BLK>>>(n);
    scan_bsums<<<1, SCAN_BLK>>>(nb);
    scan_final<<<nb, SCAN_BLK>>>(n);
    scatter_kernel<<<(E + 255) / 256, 256>>>(src, dst, E);
    // 3) gather (one warp per node, 8 warps/block)
    gat_gather<<<(n + 7) / 8, 256>>>(out, n);
}

// round 9
// speedup vs baseline: 1.2880x; 1.0332x over previous
#include <cuda_runtime.h>
#include <cuda_fp16.h>
#include <math.h>

// Problem constants (fixed-shape problem)
#define MAXN 50048
#define MAXE 1600000
#define HID 128
#define NH 8
#define HD 16
#define SCAN_BLK 256

// ---------------- device scratch (no allocation allowed) ----------------
__device__ float  g_Q[MAXN * HID];       // fp32 (read once per node)
__device__ __half g_Kh[MAXN * HID];      // fp16 (read per edge)
__device__ __half g_Vh[MAXN * HID];      // fp16 (read per edge)
__device__ int g_cnt[MAXN];              // zero-initialized; re-zeroed in scan_final
__device__ int g_off[MAXN];
__device__ int g_cur[MAXN];
__device__ int g_esrc[MAXE];
__device__ int g_bsum[512];

// ---------------- QKV GEMM (tf32 tensor cores) ---------------------------
// C[n,128] = h[n,128] @ W[128,128] + b.  Block tile 128x128, BK=32.
// 256 threads = 8 warps 2(M) x 4(N); warp tile 64x32; mma.m16n8k8.tf32.
__device__ __forceinline__ float cvt_tf32f(float v)
{
    unsigned r;
    asm("cvt.rna.tf32.f32 %0, %1;" : "=r"(r) : "f"(v));
    return __uint_as_float(r);
}

__global__ __launch_bounds__(256) void qkv_gemm(
    const float* __restrict__ h,
    const float* __restrict__ wq, const float* __restrict__ bq,
    const float* __restrict__ wk, const float* __restrict__ bk,
    const float* __restrict__ wv, const float* __restrict__ bv,
    int n)
{
    const float* W; const float* bias;
    float*  outf = 0;
    __half* outh = 0;
    if (blockIdx.y == 0)      { W = wq; bias = bq; outf = g_Q; }
    else if (blockIdx.y == 1) { W = wk; bias = bk; outh = g_Kh; }
    else                      { W = wv; bias = bv; outh = g_Vh; }

    __shared__ float As[32][132];   // [k][m], tf32-rounded
    __shared__ float Bs[32][132];   // [k][n], tf32-rounded

    const int tid  = threadIdx.x;
    const int lane = tid & 31;
    const int wid  = tid >> 5;          // 0..7
    const int wm   = wid >> 2;          // 0..1 -> M offset wm*64
    const int wn   = wid & 3;           // 0..3 -> N offset wn*32
    const int g    = lane >> 2;         // groupID 0..7
    const int tg   = lane & 3;          // thread-in-group 0..3
    const int row0 = blockIdx.x * 128;

    float c[4][4][4];
#pragma unroll
    for (int mi = 0; mi < 4; mi++)
#pragma unroll
        for (int ni = 0; ni < 4; ni++)
#pragma unroll
            for (int r = 0; r < 4; r++) c[mi][ni][r] = 0.f;

    for (int kk = 0; kk < HID; kk += 32) {
        {
            int m    = tid >> 1;
            int base = (tid & 1) * 16;
            int row  = row0 + m;
#pragma unroll
            for (int i = 0; i < 4; i++) {
                float4 v = make_float4(0.f, 0.f, 0.f, 0.f);
                if (row < n)
                    v = *(const float4*)(h + (size_t)row * HID + kk + base + i * 4);
                As[base + i * 4 + 0][m] = cvt_tf32f(v.x);
                As[base + i * 4 + 1][m] = cvt_tf32f(v.y);
                As[base + i * 4 + 2][m] = cvt_tf32f(v.z);
                As[base + i * 4 + 3][m] = cvt_tf32f(v.w);
            }
        }
        {
            int k    = tid >> 3;
            int base = (tid & 7) * 16;
#pragma unroll
            for (int i = 0; i < 4; i++) {
                float4 v = *(const float4*)(W + (size_t)(kk + k) * 128 + base + i * 4);
                Bs[k][base + i * 4 + 0] = cvt_tf32f(v.x);
                Bs[k][base + i * 4 + 1] = cvt_tf32f(v.y);
                Bs[k][base + i * 4 + 2] = cvt_tf32f(v.z);
                Bs[k][base + i * 4 + 3] = cvt_tf32f(v.w);
            }
        }
        __syncthreads();

#pragma unroll
        for (int ks = 0; ks < 4; ks++) {
            const int k0 = ks * 8;
            unsigned a[4][4];
#pragma unroll
            for (int mi = 0; mi < 4; mi++) {
                int m0 = wm * 64 + mi * 16;
                a[mi][0] = __float_as_uint(As[k0 + tg    ][m0 + g    ]);
                a[mi][1] = __float_as_uint(As[k0 + tg    ][m0 + g + 8]);
                a[mi][2] = __float_as_uint(As[k0 + tg + 4][m0 + g    ]);
                a[mi][3] = __float_as_uint(As[k0 + tg + 4][m0 + g + 8]);
            }
            unsigned b[4][2];
#pragma unroll
            for (int ni = 0; ni < 4; ni++) {
                int n0 = wn * 32 + ni * 8;
                b[ni][0] = __float_as_uint(Bs[k0 + tg    ][n0 + g]);
                b[ni][1] = __float_as_uint(Bs[k0 + tg + 4][n0 + g]);
            }
#pragma unroll
            for (int mi = 0; mi < 4; mi++)
#pragma unroll
                for (int ni = 0; ni < 4; ni++) {
                    asm volatile(
                        "mma.sync.aligned.m16n8k8.row.col.f32.tf32.tf32.f32 "
                        "{%0,%1,%2,%3}, {%4,%5,%6,%7}, {%8,%9}, {%0,%1,%2,%3};"
                        : "+f"(c[mi][ni][0]), "+f"(c[mi][ni][1]),
                          "+f"(c[mi][ni][2]), "+f"(c[mi][ni][3])
                        : "r"(a[mi][0]), "r"(a[mi][1]), "r"(a[mi][2]), "r"(a[mi][3]),
                          "r"(b[ni][0]), "r"(b[ni][1]));
                }
        }
        __syncthreads();
    }

    // epilogue: add bias, store (c0,c1 -> row g; c2,c3 -> row g+8)
#pragma unroll
    for (int ni = 0; ni < 4; ni++) {
        int col = wn * 32 + ni * 8 + tg * 2;
        float bx = bias[col], by = bias[col + 1];
#pragma unroll
        for (int mi = 0; mi < 4; mi++) {
            int rowA = row0 + wm * 64 + mi * 16 + g;
            int rowB = rowA + 8;
            if (outf) {
                if (rowA < n) {
                    float2 o = make_float2(c[mi][ni][0] + bx, c[mi][ni][1] + by);
                    *(float2*)(outf + (size_t)rowA * 128 + col) = o;
                }
                if (rowB < n) {
                    float2 o = make_float2(c[mi][ni][2] + bx, c[mi][ni][3] + by);
                    *(float2*)(outf + (size_t)rowB * 128 + col) = o;
                }
            } else {
                if (rowA < n) {
                    __half2 o = __floats2half2_rn(c[mi][ni][0] + bx, c[mi][ni][1] + by);
                    *(__half2*)(outh + (size_t)rowA * 128 + col) = o;
                }
                if (rowB < n) {
                    __half2 o = __floats2half2_rn(c[mi][ni][2] + bx, c[mi][ni][3] + by);
                    *(__half2*)(outh + (size_t)rowB * 128 + col) = o;
                }
            }
        }
    }
}

// ---------------- CSR construction --------------------------------------
__global__ void hist_kernel(const int* __restrict__ dst, int E)
{
    int i = blockIdx.x * blockDim.x + threadIdx.x;
    if (i < E) atomicAdd(&g_cnt[dst[i]], 1);
}

__global__ __launch_bounds__(SCAN_BLK) void scan_partial(int n)
{
    __shared__ int sh[SCAN_BLK];
    int i = blockIdx.x * SCAN_BLK + threadIdx.x;
    int v = (i < n) ? g_cnt[i] : 0;
    sh[threadIdx.x] = v;
    __syncthreads();
    for (int off = SCAN_BLK / 2; off > 0; off >>= 1) {
        if (threadIdx.x < off) sh[threadIdx.x] += sh[threadIdx.x + off];
        __syncthreads();
    }
    if (threadIdx.x == 0) g_bsum[blockIdx.x] = sh[0];
}

__global__ __launch_bounds__(SCAN_BLK) void scan_bsums(int nb)
{
    __shared__ int sh[SCAN_BLK];
    int t = threadIdx.x;
    int v = (t < nb) ? g_bsum[t] : 0;
    sh[t] = v;
    __syncthreads();
    for (int off = 1; off < SCAN_BLK; off <<= 1) {
        int u = (t >= off) ? sh[t - off] : 0;
        __syncthreads();
        sh[t] += u;
        __syncthreads();
    }
    if (t < nb) g_bsum[t] = sh[t] - v;   // exclusive
}

// reads g_cnt, writes g_off/g_cur, and re-zeroes g_cnt for the next call
// (statics start zeroed, every call leaves them zeroed -> deterministic).
__global__ __launch_bounds__(SCAN_BLK) void scan_final(int n)
{
    __shared__ int sh[SCAN_BLK];
    int i = blockIdx.x * SCAN_BLK + threadIdx.x;
    int t = threadIdx.x;
    int v = (i < n) ? g_cnt[i] : 0;
    sh[t] = v;
    __syncthreads();
    for (int off = 1; off < SCAN_BLK; off <<= 1) {
        int u = (t >= off) ? sh[t - off] : 0;
        __syncthreads();
        sh[t] += u;
        __syncthreads();
    }
    if (i < n) {
        int excl = sh[t] - v + g_bsum[blockIdx.x];
        g_off[i] = excl;
        g_cur[i] = excl;
        g_cnt[i] = 0;
    }
}

__global__ void scatter_kernel(const int* __restrict__ src,
                               const int* __restrict__ dst, int E)
{
    int i = blockIdx.x * blockDim.x + threadIdx.x;
    if (i < E) {
        int p = atomicAdd(&g_cur[dst[i]], 1);
        g_esrc[p] = src[i];
    }
}

// ---------------- gather: one warp per destination node ------------------
// lane l owns dims [l*4, l*4+4). head = l/4 (4 lanes x 4 dims = 16 dims/head).
// K/V in fp16 (uint2 per lane). 2-way unrolled for MLP.
__global__ __launch_bounds__(256) void gat_gather(float* __restrict__ out, int n)
{
    int warp = (blockIdx.x * blockDim.x + threadIdx.x) >> 5;
    int lane = threadIdx.x & 31;
    if (warp >= n) return;

    const int t = lane * 4;
    const int start = g_off[warp];
    const int end   = g_cur[warp];

    const float4 q = *(const float4*)(g_Q + (size_t)warp * 128 + t);

    float ax = 0.f, ay = 0.f, az = 0.f, aw = 0.f;
    float den = 0.f;

    int i = start;
    for (; i + 1 < end; i += 2) {
        int s0 = g_esrc[i];
        int s1 = g_esrc[i + 1];
        uint2 kraw0 = *(const uint2*)(g_Kh + (size_t)s0 * 128 + t);
        uint2 kraw1 = *(const uint2*)(g_Kh + (size_t)s1 * 128 + t);
        uint2 vraw0 = *(const uint2*)(g_Vh + (size_t)s0 * 128 + t);
        uint2 vraw1 = *(const uint2*)(g_Vh + (size_t)s1 * 128 + t);

        float2 k01 = __half22float2(*(__half2*)&kraw0.x);
        float2 k23 = __half22float2(*(__half2*)&kraw0.y);
        float p0 = q.x * k01.x + q.y * k01.y + q.z * k23.x + q.w * k23.y;
        float2 l01 = __half22float2(*(__half2*)&kraw1.x);
        float2 l23 = __half22float2(*(__half2*)&kraw1.y);
        float p1 = q.x * l01.x + q.y * l01.y + q.z * l23.x + q.w * l23.y;

        p0 += __shfl_xor_sync(0xFFFFFFFFu, p0, 1);
        p1 += __shfl_xor_sync(0xFFFFFFFFu, p1, 1);
        p0 += __shfl_xor_sync(0xFFFFFFFFu, p0, 2);
        p1 += __shfl_xor_sync(0xFFFFFFFFu, p1, 2);
        float e0 = __expf(p0 * 0.25f);
        float e1 = __expf(p1 * 0.25f);

        float2 v01 = __half22float2(*(__half2*)&vraw0.x);
        float2 v23 = __half22float2(*(__half2*)&vraw0.y);
        float2 w01 = __half22float2(*(__half2*)&vraw1.x);
        float2 w23 = __half22float2(*(__half2*)&vraw1.y);
        ax = fmaf(e0, v01.x, fmaf(e1, w01.x, ax));
        ay = fmaf(e0, v01.y, fmaf(e1, w01.y, ay));
        az = fmaf(e0, v23.x, fmaf(e1, w23.x, az));
        aw = fmaf(e0, v23.y, fmaf(e1, w23.y, aw));
        den += e0 + e1;
    }
    if (i < end) {
        int s = g_esrc[i];
        uint2 kraw = *(const uint2*)(g_Kh + (size_t)s * 128 + t);
        float2 k01 = __half22float2(*(__half2*)&kraw.x);
        float2 k23 = __half22float2(*(__half2*)&kraw.y);
        float p = q.x * k01.x + q.y * k01.y + q.z * k23.x + q.w * k23.y;
        p += __shfl_xor_sync(0xFFFFFFFFu, p, 1);
        p += __shfl_xor_sync(0xFFFFFFFFu, p, 2);
        float e = __expf(p * 0.25f);
        uint2 vraw = *(const uint2*)(g_Vh + (size_t)s * 128 + t);
        float2 v01 = __half22float2(*(__half2*)&vraw.x);
        float2 v23 = __half22float2(*(__half2*)&vraw.y);
        ax = fmaf(e, v01.x, ax);
        ay = fmaf(e, v01.y, ay);
        az = fmaf(e, v23.x, az);
        aw = fmaf(e, v23.y, aw);
        den += e;
    }

    float inv = 1.f / den;
    float4 o;
    o.x = ax * inv; o.y = ay * inv; o.z = az * inv; o.w = aw * inv;
    *(float4*)(out + (size_t)warp * 128 + t) = o;
}

// ---------------- launch ------------------------------------------------
// Side stream + events: created lazily on FIRST call (the uncaptured
// correctness run) — NOT at static-init time (no CUDA calls before main,
// no device-memory allocation). Subsequent calls (incl. graph capture)
// submit identical work, so kernel_launch stays deterministic.
struct ForkResources {
    cudaStream_t s1;
    cudaEvent_t evFork, evJoin;
    ForkResources() {
        cudaStreamCreateWithFlags(&s1, cudaStreamNonBlocking);
        cudaEventCreateWithFlags(&evFork, cudaEventDisableTiming);
        cudaEventCreateWithFlags(&evJoin, cudaEventDisableTiming);
    }
};

extern "C" void kernel_launch(void* const* d_in, const int* in_sizes, int n_in,
                              void* d_out, int out_size)
{
    static ForkResources fork;   // constructed on first call, after harness init

    const float* h  = (const float*)d_in[0];
    const float* wq = (const float*)d_in[1];
    const float* bq = (const float*)d_in[2];
    const float* wk = (const float*)d_in[3];
    const float* bk = (const float*)d_in[4];
    const float* wv = (const float*)d_in[5];
    const float* bv = (const float*)d_in[6];
    const int*  src = (const int*)d_in[7];
    const int*  dst = (const int*)d_in[8];

    const int n = in_sizes[0] / HID;
    const int E = in_sizes[7];
    const int nb = (n + SCAN_BLK - 1) / SCAN_BLK;

    float* out = (float*)d_out;

    // Fork: CSR build on side stream, GEMM on main stream (independent work,
    // disjoint resources: tensor/smem vs L2 atomics). Joined before gather.
    cudaEventRecord(fork.evFork, 0);
    cudaStreamWaitEvent(fork.s1, fork.evFork, 0);

    // Branch B (side stream): CSR build
    hist_kernel<<<(E + 255) / 256, 256, 0, fork.s1>>>(dst, E);
    scan_partial<<<nb, SCAN_BLK, 0, fork.s1>>>(n);
    scan_bsums<<<1, SCAN_BLK, 0, fork.s1>>>(nb);
    scan_final<<<nb, SCAN_BLK, 0, fork.s1>>>(n);
    scatter_kernel<<<(E + 255) / 256, 256, 0, fork.s1>>>(src, dst, E);
    cudaEventRecord(fork.evJoin, fork.s1);

    // Branch A (main stream): Q,K,V GEMMs
    {
        dim3 grid((n + 127) / 128, 3);
        qkv_gemm<<<grid, 256>>>(h, wq, bq, wk, bk, wv, bv, n);
    }

    // Join, then gather (needs Q/K/V + CSR)
    cudaStreamWaitEvent(0, fork.evJoin, 0);
    gat_gather<<<(n + 7) / 8, 256>>>(out, n);
}

// round 10
// speedup vs baseline: 1.3501x; 1.0481x over previous
#include <cuda_runtime.h>
#include <cuda_fp16.h>
#include <math.h>

// Problem constants (fixed-shape problem)
#define MAXN 50048
#define MAXE 1600000
#define HID 128
#define NH 8
#define HD 16
#define SCAN_BLK 256

// ---------------- device scratch (no allocation allowed) ----------------
__device__ float  g_Q[MAXN * HID];        // fp32 (read once per node)
// Interleaved K/V fp16: per node 256 halves; group g (=dim/4) at offset
// g*8: [K0 K1 K2 K3 V0 V1 V2 V3]. One uint4 per lane per edge.
__device__ __half g_KV[MAXN * 2 * HID];
__device__ int g_cnt[MAXN];               // zero-init; re-zeroed in scan_final
__device__ int g_off[MAXN];
__device__ int g_cur[MAXN];
__device__ int g_esrc[MAXE];
__device__ int g_bsum[512];

// ---------------- QKV GEMM (tf32 tensor cores) ---------------------------
// C[n,128] = h[n,128] @ W[128,128] + b.  Block tile 128x128, BK=32.
// 256 threads = 8 warps 2(M) x 4(N); warp tile 64x32; mma.m16n8k8.tf32.
__device__ __forceinline__ float cvt_tf32f(float v)
{
    unsigned r;
    asm("cvt.rna.tf32.f32 %0, %1;" : "=r"(r) : "f"(v));
    return __uint_as_float(r);
}

__global__ __launch_bounds__(256) void qkv_gemm(
    const float* __restrict__ h,
    const float* __restrict__ wq, const float* __restrict__ bq,
    const float* __restrict__ wk, const float* __restrict__ bk,
    const float* __restrict__ wv, const float* __restrict__ bv,
    int n)
{
    const float* W; const float* bias;
    float* outf = 0;
    int kvOff = 0;            // 0 for K, 4 for V (within 8-half group)
    if (blockIdx.y == 0)      { W = wq; bias = bq; outf = g_Q; }
    else if (blockIdx.y == 1) { W = wk; bias = bk; kvOff = 0; }
    else                      { W = wv; bias = bv; kvOff = 4; }

    __shared__ float As[32][132];   // [k][m], tf32-rounded
    __shared__ float Bs[32][132];   // [k][n], tf32-rounded

    const int tid  = threadIdx.x;
    const int lane = tid & 31;
    const int wid  = tid >> 5;          // 0..7
    const int wm   = wid >> 2;          // 0..1 -> M offset wm*64
    const int wn   = wid & 3;           // 0..3 -> N offset wn*32
    const int g    = lane >> 2;         // groupID 0..7
    const int tg   = lane & 3;          // thread-in-group 0..3
    const int row0 = blockIdx.x * 128;

    float c[4][4][4];
#pragma unroll
    for (int mi = 0; mi < 4; mi++)
#pragma unroll
        for (int ni = 0; ni < 4; ni++)
#pragma unroll
            for (int r = 0; r < 4; r++) c[mi][ni][r] = 0.f;

    for (int kk = 0; kk < HID; kk += 32) {
        {
            int m    = tid >> 1;
            int base = (tid & 1) * 16;
            int row  = row0 + m;
#pragma unroll
            for (int i = 0; i < 4; i++) {
                float4 v = make_float4(0.f, 0.f, 0.f, 0.f);
                if (row < n)
                    v = *(const float4*)(h + (size_t)row * HID + kk + base + i * 4);
                As[base + i * 4 + 0][m] = cvt_tf32f(v.x);
                As[base + i * 4 + 1][m] = cvt_tf32f(v.y);
                As[base + i * 4 + 2][m] = cvt_tf32f(v.z);
                As[base + i * 4 + 3][m] = cvt_tf32f(v.w);
            }
        }
        {
            int k    = tid >> 3;
            int base = (tid & 7) * 16;
#pragma unroll
            for (int i = 0; i < 4; i++) {
                float4 v = *(const float4*)(W + (size_t)(kk + k) * 128 + base + i * 4);
                Bs[k][base + i * 4 + 0] = cvt_tf32f(v.x);
                Bs[k][base + i * 4 + 1] = cvt_tf32f(v.y);
                Bs[k][base + i * 4 + 2] = cvt_tf32f(v.z);
                Bs[k][base + i * 4 + 3] = cvt_tf32f(v.w);
            }
        }
        __syncthreads();

#pragma unroll
        for (int ks = 0; ks < 4; ks++) {
            const int k0 = ks * 8;
            unsigned a[4][4];
#pragma unroll
            for (int mi = 0; mi < 4; mi++) {
                int m0 = wm * 64 + mi * 16;
                a[mi][0] = __float_as_uint(As[k0 + tg    ][m0 + g    ]);
                a[mi][1] = __float_as_uint(As[k0 + tg    ][m0 + g + 8]);
                a[mi][2] = __float_as_uint(As[k0 + tg + 4][m0 + g    ]);
                a[mi][3] = __float_as_uint(As[k0 + tg + 4][m0 + g + 8]);
            }
            unsigned b[4][2];
#pragma unroll
            for (int ni = 0; ni < 4; ni++) {
                int n0 = wn * 32 + ni * 8;
                b[ni][0] = __float_as_uint(Bs[k0 + tg    ][n0 + g]);
                b[ni][1] = __float_as_uint(Bs[k0 + tg + 4][n0 + g]);
            }
#pragma unroll
            for (int mi = 0; mi < 4; mi++)
#pragma unroll
                for (int ni = 0; ni < 4; ni++) {
                    asm volatile(
                        "mma.sync.aligned.m16n8k8.row.col.f32.tf32.tf32.f32 "
                        "{%0,%1,%2,%3}, {%4,%5,%6,%7}, {%8,%9}, {%0,%1,%2,%3};"
                        : "+f"(c[mi][ni][0]), "+f"(c[mi][ni][1]),
                          "+f"(c[mi][ni][2]), "+f"(c[mi][ni][3])
                        : "r"(a[mi][0]), "r"(a[mi][1]), "r"(a[mi][2]), "r"(a[mi][3]),
                          "r"(b[ni][0]), "r"(b[ni][1]));
                }
        }
        __syncthreads();
    }

    // epilogue: add bias, store (c0,c1 -> row g; c2,c3 -> row g+8)
#pragma unroll
    for (int ni = 0; ni < 4; ni++) {
        int col = wn * 32 + ni * 8 + tg * 2;
        float bx = bias[col], by = bias[col + 1];
        // interleaved half index within node: (col/4)*8 + (col%4) + kvOff
        int kvIdx = ((col >> 2) << 3) + (col & 3) + kvOff;
#pragma unroll
        for (int mi = 0; mi < 4; mi++) {
            int rowA = row0 + wm * 64 + mi * 16 + g;
            int rowB = rowA + 8;
            if (outf) {
                if (rowA < n) {
                    float2 o = make_float2(c[mi][ni][0] + bx, c[mi][ni][1] + by);
                    *(float2*)(outf + (size_t)rowA * 128 + col) = o;
                }
                if (rowB < n) {
                    float2 o = make_float2(c[mi][ni][2] + bx, c[mi][ni][3] + by);
                    *(float2*)(outf + (size_t)rowB * 128 + col) = o;
                }
            } else {
                if (rowA < n) {
                    __half2 o = __floats2half2_rn(c[mi][ni][0] + bx, c[mi][ni][1] + by);
                    *(__half2*)(g_KV + (size_t)rowA * 256 + kvIdx) = o;
                }
                if (rowB < n) {
                    __half2 o = __floats2half2_rn(c[mi][ni][2] + bx, c[mi][ni][3] + by);
                    *(__half2*)(g_KV + (size_t)rowB * 256 + kvIdx) = o;
                }
            }
        }
    }
}

// ---------------- CSR construction --------------------------------------
__global__ void hist_kernel(const int* __restrict__ dst, int E)
{
    int i = blockIdx.x * blockDim.x + threadIdx.x;
    if (i < E) atomicAdd(&g_cnt[dst[i]], 1);
}

__global__ __launch_bounds__(SCAN_BLK) void scan_partial(int n)
{
    __shared__ int sh[SCAN_BLK];
    int i = blockIdx.x * SCAN_BLK + threadIdx.x;
    int v = (i < n) ? g_cnt[i] : 0;
    sh[threadIdx.x] = v;
    __syncthreads();
    for (int off = SCAN_BLK / 2; off > 0; off >>= 1) {
        if (threadIdx.x < off) sh[threadIdx.x] += sh[threadIdx.x + off];
        __syncthreads();
    }
    if (threadIdx.x == 0) g_bsum[blockIdx.x] = sh[0];
}

__global__ __launch_bounds__(SCAN_BLK) void scan_bsums(int nb)
{
    __shared__ int sh[SCAN_BLK];
    int t = threadIdx.x;
    int v = (t < nb) ? g_bsum[t] : 0;
    sh[t] = v;
    __syncthreads();
    for (int off = 1; off < SCAN_BLK; off <<= 1) {
        int u = (t >= off) ? sh[t - off] : 0;
        __syncthreads();
        sh[t] += u;
        __syncthreads();
    }
    if (t < nb) g_bsum[t] = sh[t] - v;   // exclusive
}

// reads g_cnt, writes g_off/g_cur, re-zeroes g_cnt (deterministic replay).
__global__ __launch_bounds__(SCAN_BLK) void scan_final(int n)
{
    __shared__ int sh[SCAN_BLK];
    int i = blockIdx.x * SCAN_BLK + threadIdx.x;
    int t = threadIdx.x;
    int v = (i < n) ? g_cnt[i] : 0;
    sh[t] = v;
    __syncthreads();
    for (int off = 1; off < SCAN_BLK; off <<= 1) {
        int u = (t >= off) ? sh[t - off] : 0;
        __syncthreads();
        sh[t] += u;
        __syncthreads();
    }
    if (i < n) {
        int excl = sh[t] - v + g_bsum[blockIdx.x];
        g_off[i] = excl;
        g_cur[i] = excl;
        g_cnt[i] = 0;
    }
}

__global__ void scatter_kernel(const int* __restrict__ src,
                               const int* __restrict__ dst, int E)
{
    int i = blockIdx.x * blockDim.x + threadIdx.x;
    if (i < E) {
        int p = atomicAdd(&g_cur[dst[i]], 1);
        g_esrc[p] = src[i];
    }
}

// ---------------- gather: one warp per destination node ------------------
// lane l owns dims [l*4, l*4+4). Interleaved KV: ONE uint4 (16B) per edge
// per lane = K0..3 | V0..3.  2-way unrolled.
__global__ __launch_bounds__(256) void gat_gather(float* __restrict__ out, int n)
{
    int warp = (blockIdx.x * blockDim.x + threadIdx.x) >> 5;
    int lane = threadIdx.x & 31;
    if (warp >= n) return;

    const int t = lane * 4;
    const int start = g_off[warp];
    const int end   = g_cur[warp];

    const float4 q = *(const float4*)(g_Q + (size_t)warp * 128 + t);

    float ax = 0.f, ay = 0.f, az = 0.f, aw = 0.f;
    float den = 0.f;

    int i = start;
    for (; i + 1 < end; i += 2) {
        int s0 = g_esrc[i];
        int s1 = g_esrc[i + 1];
        uint4 kv0 = *(const uint4*)(g_KV + (size_t)s0 * 256 + lane * 8);
        uint4 kv1 = *(const uint4*)(g_KV + (size_t)s1 * 256 + lane * 8);

        float2 k01 = __half22float2(*(__half2*)&kv0.x);
        float2 k23 = __half22float2(*(__half2*)&kv0.y);
        float p0 = q.x * k01.x + q.y * k01.y + q.z * k23.x + q.w * k23.y;
        float2 l01 = __half22float2(*(__half2*)&kv1.x);
        float2 l23 = __half22float2(*(__half2*)&kv1.y);
        float p1 = q.x * l01.x + q.y * l01.y + q.z * l23.x + q.w * l23.y;

        p0 += __shfl_xor_sync(0xFFFFFFFFu, p0, 1);
        p1 += __shfl_xor_sync(0xFFFFFFFFu, p1, 1);
        p0 += __shfl_xor_sync(0xFFFFFFFFu, p0, 2);
        p1 += __shfl_xor_sync(0xFFFFFFFFu, p1, 2);
        float e0 = __expf(p0 * 0.25f);
        float e1 = __expf(p1 * 0.25f);

        float2 v01 = __half22float2(*(__half2*)&kv0.z);
        float2 v23 = __half22float2(*(__half2*)&kv0.w);
        float2 w01 = __half22float2(*(__half2*)&kv1.z);
        float2 w23 = __half22float2(*(__half2*)&kv1.w);
        ax = fmaf(e0, v01.x, fmaf(e1, w01.x, ax));
        ay = fmaf(e0, v01.y, fmaf(e1, w01.y, ay));
        az = fmaf(e0, v23.x, fmaf(e1, w23.x, az));
        aw = fmaf(e0, v23.y, fmaf(e1, w23.y, aw));
        den += e0 + e1;
    }
    if (i < end) {
        int s = g_esrc[i];
        uint4 kv = *(const uint4*)(g_KV + (size_t)s * 256 + lane * 8);
        float2 k01 = __half22float2(*(__half2*)&kv.x);
        float2 k23 = __half22float2(*(__half2*)&kv.y);
        float p = q.x * k01.x + q.y * k01.y + q.z * k23.x + q.w * k23.y;
        p += __shfl_xor_sync(0xFFFFFFFFu, p, 1);
        p += __shfl_xor_sync(0xFFFFFFFFu, p, 2);
        float e = __expf(p * 0.25f);
        float2 v01 = __half22float2(*(__half2*)&kv.z);
        float2 v23 = __half22float2(*(__half2*)&kv.w);
        ax = fmaf(e, v01.x, ax);
        ay = fmaf(e, v01.y, ay);
        az = fmaf(e, v23.x, az);
        aw = fmaf(e, v23.y, aw);
        den += e;
    }

    float inv = 1.f / den;
    float4 o;
    o.x = ax * inv; o.y = ay * inv; o.z = az * inv; o.w = aw * inv;
    *(float4*)(out + (size_t)warp * 128 + t) = o;
}

// ---------------- launch ------------------------------------------------
// Side stream + events: created lazily on FIRST call (uncaptured correctness
// run), not at static-init. Same work submitted every call -> deterministic.
struct ForkResources {
    cudaStream_t s1;
    cudaEvent_t evFork, evJoin;
    ForkResources() {
        cudaStreamCreateWithFlags(&s1, cudaStreamNonBlocking);
        cudaEventCreateWithFlags(&evFork, cudaEventDisableTiming);
        cudaEventCreateWithFlags(&evJoin, cudaEventDisableTiming);
    }
};

extern "C" void kernel_launch(void* const* d_in, const int* in_sizes, int n_in,
                              void* d_out, int out_size)
{
    static ForkResources fork;   // first call, after harness init

    const float* h  = (const float*)d_in[0];
    const float* wq = (const float*)d_in[1];
    const float* bq = (const float*)d_in[2];
    const float* wk = (const float*)d_in[3];
    const float* bk = (const float*)d_in[4];
    const float* wv = (const float*)d_in[5];
    const float* bv = (const float*)d_in[6];
    const int*  src = (const int*)d_in[7];
    const int*  dst = (const int*)d_in[8];

    const int n = in_sizes[0] / HID;
    const int E = in_sizes[7];
    const int nb = (n + SCAN_BLK - 1) / SCAN_BLK;

    float* out = (float*)d_out;

    // Fork: CSR build on side stream, GEMM on main stream. Join before gather.
    cudaEventRecord(fork.evFork, 0);
    cudaStreamWaitEvent(fork.s1, fork.evFork, 0);

    hist_kernel<<<(E + 255) / 256, 256, 0, fork.s1>>>(dst, E);
    scan_partial<<<nb, SCAN_BLK, 0, fork.s1>>>(n);
    scan_bsums<<<1, SCAN_BLK, 0, fork.s1>>>(nb);
    scan_final<<<nb, SCAN_BLK, 0, fork.s1>>>(n);
    scatter_kernel<<<(E + 255) / 256, 256, 0, fork.s1>>>(src, dst, E);
    cudaEventRecord(fork.evJoin, fork.s1);

    {
        dim3 grid((n + 127) / 128, 3);
        qkv_gemm<<<grid, 256>>>(h, wq, bq, wk, bk, wv, bv, n);
    }

    cudaStreamWaitEvent(0, fork.evJoin, 0);
    gat_gather<<<(n + 7) / 8, 256>>>(out, n);
}